// round 10
// baseline (speedup 1.0000x reference)
#include <cuda_runtime.h>
#include <cuda_bf16.h>
#include <math.h>
#include <stdint.h>

#define N 8192
#define D 512
#define TM 128           // M rows per CTA
#define TNT 256          // cols per column tile
#define KC 64            // K chunk per B SMEM tile
#define KTOP 5
#define NTILES ((N / 2) / TNT)   // 8 column tiles per CTA (half the matrix)

// Scratch (no cudaMalloc allowed)
static __device__ __nv_bfloat16 g_xnb[(size_t)N * D];   // 8 MB normalized rows, bf16
static __device__ float g_top[(size_t)N * 10];          // per-row top5 from each half
static __device__ float g_logrho[N];

// SMEM: A panel 128 KB + 2x 32 KB B buffers + 10 KB running top-5 lists
#define SA_BYTES (128 * 1024)
#define SB_BYTES (32 * 1024)
#define SG_OFF   (SA_BYTES + 2 * SB_BYTES)         // 196608
#define SMEM_TOTAL (SG_OFF + 128 * 4 * 5 * 4)      // 206848

// ---- PTX helpers ------------------------------------------------------------
__device__ __forceinline__ uint32_t smem_u32(const void* p) {
    uint32_t a;
    asm("{ .reg .u64 t; cvta.to.shared.u64 t, %1; cvt.u32.u64 %0, t; }" : "=r"(a) : "l"(p));
    return a;
}
__device__ __forceinline__ void ldsm_x4(uint32_t* r, uint32_t addr) {
    asm volatile("ldmatrix.sync.aligned.m8n8.x4.shared.b16 {%0,%1,%2,%3}, [%4];"
                 : "=r"(r[0]), "=r"(r[1]), "=r"(r[2]), "=r"(r[3]) : "r"(addr));
}
__device__ __forceinline__ void mma_bf16(float* d, const uint32_t* a,
                                         uint32_t b0, uint32_t b1) {
    asm volatile(
        "mma.sync.aligned.m16n8k16.row.col.f32.bf16.bf16.f32 "
        "{%0,%1,%2,%3}, {%4,%5,%6,%7}, {%8,%9}, {%0,%1,%2,%3};"
        : "+f"(d[0]), "+f"(d[1]), "+f"(d[2]), "+f"(d[3])
        : "r"(a[0]), "r"(a[1]), "r"(a[2]), "r"(a[3]), "r"(b0), "r"(b1));
}
__device__ __forceinline__ void cp16(uint32_t dst, const void* src) {
    asm volatile("cp.async.cg.shared.global [%0], [%1], 16;" :: "r"(dst), "l"(src));
}
__device__ __forceinline__ void cp_commit() {
    asm volatile("cp.async.commit_group;" ::: "memory");
}
__device__ __forceinline__ void cp_wait1() {
    asm volatile("cp.async.wait_group 1;" ::: "memory");
}
__device__ __forceinline__ void cp_wait0() {
    asm volatile("cp.async.wait_group 0;" ::: "memory");
}
// insert v into ascending 5-list (t0 = smallest kept)
__device__ __forceinline__ void ins5(float v, float& t0, float& t1, float& t2,
                                     float& t3, float& t4) {
    if (v > t0) {
        t0 = v;
        if (t0 > t1) { float tm = t0; t0 = t1; t1 = tm;
          if (t1 > t2) { tm = t1; t1 = t2; t2 = tm;
            if (t2 > t3) { tm = t2; t2 = t3; t3 = tm;
              if (t3 > t4) { tm = t3; t3 = t4; t4 = tm; } } } }
    }
}

// ---------------------------------------------------------------------------
// Kernel 1: row-normalize + cast to bf16. One block (128 threads) per row.
// ---------------------------------------------------------------------------
__global__ void knorm(const float* __restrict__ x, __nv_bfloat16* __restrict__ xnb) {
    int row = blockIdx.x;
    int t = threadIdx.x;
    float4 v = ((const float4*)(x + (size_t)row * D))[t];
    float s = v.x * v.x + v.y * v.y + v.z * v.z + v.w * v.w;
    #pragma unroll
    for (int o = 16; o; o >>= 1) s += __shfl_xor_sync(0xffffffffu, s, o);
    __shared__ float ws[4];
    if ((t & 31) == 0) ws[t >> 5] = s;
    __syncthreads();
    float inv = rsqrtf(ws[0] + ws[1] + ws[2] + ws[3]);
    __nv_bfloat162 p0 = __floats2bfloat162_rn(v.x * inv, v.y * inv);
    __nv_bfloat162 p1 = __floats2bfloat162_rn(v.z * inv, v.w * inv);
    uint2 o2;
    o2.x = *(uint32_t*)&p0;
    o2.y = *(uint32_t*)&p1;
    ((uint2*)(xnb + (size_t)row * D))[t] = o2;
}

// ---------------------------------------------------------------------------
// Kernel 2: mma.sync bf16 GEMM (Xn Xn^T) + fused per-row top-5.
// Grid (64, 2). 256 threads = 8 warps (2M x 4N), warp tile 64x64.
// Running top-5 lists live in SMEM per (row, N-warp-group); per-tile scan
// uses transient registers only -> mainloop stays under ~190 regs, kb loop
// not unrolled to keep the body inside the I-cache.
// ---------------------------------------------------------------------------
__global__ void __launch_bounds__(256, 1)
gemm_topk(const __nv_bfloat16* __restrict__ xnb, float* __restrict__ gtop) {
    extern __shared__ char smem[];
    const uint32_t sb = smem_u32(smem);
    float* sgrp = (float*)(smem + SG_OFF);   // [128][4][5] running lists
    const int tid = threadIdx.x;
    const int wid = tid >> 5, lane = tid & 31;
    const int wm = wid & 1;          // 2 M-groups of 64 rows
    const int wn = wid >> 1;         // 4 N-groups of 64 cols
    const int brow = blockIdx.x * TM;
    const int colbase = blockIdx.y * (N / 2);

    const int q = lane >> 3;
    const int lr = lane & 7;
    const uint32_t swz = (uint32_t)lr << 4;

    // init running lists
    for (int i = tid; i < 128 * 4 * 5; i += 256) sgrp[i] = -2.f;

    // ---- Load resident A panel: 128 rows x 512 bf16, swizzled ----
    #pragma unroll 8
    for (int it = 0; it < 32; it++) {
        int idx = tid + it * 256;
        int r = idx >> 6, c16 = idx & 63;
        uint32_t off = (uint32_t)r * 1024 + (uint32_t)c16 * 16;
        uint32_t sw = off ^ ((uint32_t)(r & 7) << 4);
        *(uint4*)(smem + sw) = *(const uint4*)(xnb + (size_t)(brow + r) * D + c16 * 8);
    }

    uint32_t aoff[4], boff[4];
    #pragma unroll
    for (int mt = 0; mt < 4; mt++) {
        int arow = wm * 64 + mt * 16 + (q & 1) * 8 + lr;
        aoff[mt] = (uint32_t)arow * 1024 + (uint32_t)(q >> 1) * 16;
    }
    #pragma unroll
    for (int np = 0; np < 4; np++) {
        int bn = wn * 64 + np * 16 + (q & 1) * 8 + lr;
        boff[np] = (uint32_t)bn * 128 + (uint32_t)(q >> 1) * 16;
    }

    // preload tile0 chunk0 into buf0
    #pragma unroll
    for (int it = 0; it < 8; it++) {
        int idx = tid + it * 256;
        int n = idx >> 3, c16 = idx & 7;
        uint32_t off = (uint32_t)n * 128 + (uint32_t)c16 * 16;
        uint32_t sw = off ^ ((uint32_t)(n & 7) << 4);
        cp16(sb + SA_BYTES + sw, xnb + (size_t)(colbase + n) * D + c16 * 8);
    }
    cp_commit();

    for (int ct = 0; ct < NTILES; ct++) {
        const int col0 = colbase + ct * TNT;

        float acc[4][8][4];
        #pragma unroll
        for (int mt = 0; mt < 4; mt++)
            #pragma unroll
            for (int nt = 0; nt < 8; nt++)
                #pragma unroll
                for (int j = 0; j < 4; j++) acc[mt][nt][j] = 0.f;

        #pragma unroll 1
        for (int kb = 0; kb < D / KC; kb++) {
            if (kb < 7) {
                uint32_t dstb = sb + SA_BYTES + ((kb + 1) & 1) * SB_BYTES;
                #pragma unroll
                for (int it = 0; it < 8; it++) {
                    int idx = tid + it * 256;
                    int n = idx >> 3, c16 = idx & 7;
                    uint32_t off = (uint32_t)n * 128 + (uint32_t)c16 * 16;
                    uint32_t sw = off ^ ((uint32_t)(n & 7) << 4);
                    cp16(dstb + sw, xnb + (size_t)(col0 + n) * D + (kb + 1) * KC + c16 * 8);
                }
                cp_commit();
                cp_wait1();
            } else if (ct + 1 < NTILES) {
                uint32_t dstb = sb + SA_BYTES;
                int ncol0 = colbase + (ct + 1) * TNT;
                #pragma unroll
                for (int it = 0; it < 8; it++) {
                    int idx = tid + it * 256;
                    int n = idx >> 3, c16 = idx & 7;
                    uint32_t off = (uint32_t)n * 128 + (uint32_t)c16 * 16;
                    uint32_t sw = off ^ ((uint32_t)(n & 7) << 4);
                    cp16(dstb + sw, xnb + (size_t)(ncol0 + n) * D + c16 * 8);
                }
                cp_commit();
                cp_wait1();
            } else {
                cp_wait0();
            }
            __syncthreads();

            const uint32_t bbase = sb + SA_BYTES + (kb & 1) * SB_BYTES;

            #pragma unroll
            for (int k16 = 0; k16 < 4; k16++) {
                uint32_t b[4][4];
                #pragma unroll
                for (int np = 0; np < 4; np++)
                    ldsm_x4(b[np], bbase + ((boff[np] + k16 * 32) ^ swz));
                #pragma unroll
                for (int mt = 0; mt < 4; mt++) {
                    uint32_t a[4];
                    ldsm_x4(a, sb + ((aoff[mt] + kb * 128 + k16 * 32) ^ swz));
                    #pragma unroll
                    for (int nt = 0; nt < 8; nt++) {
                        const int np = nt >> 1, w = nt & 1;
                        mma_bf16(acc[mt][nt], a, b[np][w], b[np][w + 2]);
                    }
                }
            }
            __syncthreads();
        }

        // ---- per-tile scan: transient top-5, merged into SMEM running lists
        #pragma unroll
        for (int mt = 0; mt < 4; mt++)
            #pragma unroll
            for (int half = 0; half < 2; half++) {
                const int rl = wm * 64 + mt * 16 + half * 8 + (lane >> 2);
                const int rg = brow + rl;
                float l0 = -2.f, l1 = -2.f, l2 = -2.f, l3 = -2.f, l4 = -2.f;
                #pragma unroll
                for (int nt = 0; nt < 8; nt++)
                    #pragma unroll
                    for (int j = 0; j < 2; j++) {
                        float v = acc[mt][nt][half * 2 + j];
                        int cg = col0 + wn * 64 + nt * 8 + 2 * (lane & 3) + j;
                        if (cg != rg) ins5(v, l0, l1, l2, l3, l4);
                    }
                float* L = sgrp + (rl * 4 + wn) * 5;
                #pragma unroll
                for (int r = 0; r < 4; r++) {
                    if ((lane & 3) == r) {
                        float m0 = L[0], m1 = L[1], m2 = L[2], m3 = L[3], m4 = L[4];
                        ins5(l0, m0, m1, m2, m3, m4);
                        ins5(l1, m0, m1, m2, m3, m4);
                        ins5(l2, m0, m1, m2, m3, m4);
                        ins5(l3, m0, m1, m2, m3, m4);
                        ins5(l4, m0, m1, m2, m3, m4);
                        L[0] = m0; L[1] = m1; L[2] = m2; L[3] = m3; L[4] = m4;
                    }
                    __syncwarp();
                }
            }
        __syncthreads();  // lists settled before next tile (and before final merge)
    }

    // ---- final merge: 4 group lists per row -> top-5 -> gmem ----
    if (tid < 128) {
        float t0 = -2.f, t1 = -2.f, t2 = -2.f, t3 = -2.f, t4 = -2.f;
        #pragma unroll
        for (int i = 0; i < 20; i++)
            ins5(sgrp[tid * 20 + i], t0, t1, t2, t3, t4);
        float* dst = gtop + (size_t)(brow + tid) * 10 + blockIdx.y * 5;
        dst[0] = t0; dst[1] = t1; dst[2] = t2; dst[3] = t3; dst[4] = t4;
    }
}

// ---------------------------------------------------------------------------
// Kernel 3: merge the two halves' top-5 lists, compute log(mean_rho + eps).
// ---------------------------------------------------------------------------
__global__ void kfinal(const float* __restrict__ gtop, float* __restrict__ lr) {
    int row = blockIdx.x * 256 + threadIdx.x;
    float v[10];
    #pragma unroll
    for (int i = 0; i < 10; i++) v[i] = gtop[(size_t)row * 10 + i];
    float sum = 0.f;
    #pragma unroll
    for (int s = 0; s < KTOP; s++) {
        int bi = 0; float bv = v[0];
        #pragma unroll
        for (int i = 1; i < 10; i++)
            if (v[i] > bv) { bv = v[i]; bi = i; }
        v[bi] = -9.f;
        sum += sqrtf(fmaxf(2.f - 2.f * bv, 0.f));
    }
    lr[row] = logf(sum * (1.f / KTOP) + 1e-8f);
}

// ---------------------------------------------------------------------------
// Kernel 4: out = -mean(logrho)
// ---------------------------------------------------------------------------
__global__ void kred(const float* __restrict__ lr, float* __restrict__ out) {
    int t = threadIdx.x;
    float s = 0.f;
    for (int i = t; i < N; i += 256) s += lr[i];
    #pragma unroll
    for (int o = 16; o; o >>= 1) s += __shfl_xor_sync(0xffffffffu, s, o);
    __shared__ float ws[8];
    if ((t & 31) == 0) ws[t >> 5] = s;
    __syncthreads();
    if (t == 0) {
        float tot = 0.f;
        #pragma unroll
        for (int i = 0; i < 8; i++) tot += ws[i];
        out[0] = -tot / (float)N;
    }
}

// ---------------------------------------------------------------------------
extern "C" void kernel_launch(void* const* d_in, const int* in_sizes, int n_in,
                              void* d_out, int out_size) {
    (void)in_sizes; (void)n_in; (void)out_size;
    const float* x = (const float*)d_in[0];
    float* out = (float*)d_out;

    __nv_bfloat16* xnb; cudaGetSymbolAddress((void**)&xnb, g_xnb);
    float* gtop;        cudaGetSymbolAddress((void**)&gtop, g_top);
    float* lrho;        cudaGetSymbolAddress((void**)&lrho, g_logrho);

    cudaFuncSetAttribute(gemm_topk, cudaFuncAttributeMaxDynamicSharedMemorySize, SMEM_TOTAL);

    knorm<<<N, 128>>>(x, xnb);
    gemm_topk<<<dim3(N / TM, 2), 256, SMEM_TOTAL>>>(xnb, gtop);
    kfinal<<<N / 256, 256>>>(gtop, lrho);
    kred<<<1, 256>>>(lrho, out);
}

// round 11
// speedup vs baseline: 2.1557x; 2.1557x over previous
#include <cuda_runtime.h>
#include <cuda_bf16.h>
#include <math.h>
#include <stdint.h>

#define N 8192
#define D 512
#define TM 128           // M rows per CTA
#define TNT 128          // cols per column tile
#define KC 64            // K chunk per B SMEM tile
#define KTOP 5
#define NTILES ((N / 2) / TNT)      // 32 column tiles per CTA (half the matrix)
#define NCHUNK (NTILES * (D / KC))  // 256 total K-chunks per CTA

// Scratch (no cudaMalloc allowed)
static __device__ __nv_bfloat16 g_xnb[(size_t)N * D];   // 8 MB normalized rows, bf16
static __device__ float g_top[(size_t)N * 10];          // per-row top5 from each half
static __device__ float g_logrho[N];

// SMEM: A panel 128 KB resident + 3x 16 KB B buffers (merge area reuses A)
#define SA_BYTES (128 * 1024)
#define SB_BYTES (16 * 1024)
#define SMEM_TOTAL (SA_BYTES + 3 * SB_BYTES)   // 176 KB

// ---- PTX helpers ------------------------------------------------------------
__device__ __forceinline__ uint32_t smem_u32(const void* p) {
    uint32_t a;
    asm("{ .reg .u64 t; cvta.to.shared.u64 t, %1; cvt.u32.u64 %0, t; }" : "=r"(a) : "l"(p));
    return a;
}
__device__ __forceinline__ void ldsm_x4(uint32_t* r, uint32_t addr) {
    asm volatile("ldmatrix.sync.aligned.m8n8.x4.shared.b16 {%0,%1,%2,%3}, [%4];"
                 : "=r"(r[0]), "=r"(r[1]), "=r"(r[2]), "=r"(r[3]) : "r"(addr));
}
__device__ __forceinline__ void mma_bf16(float* d, const uint32_t* a,
                                         uint32_t b0, uint32_t b1) {
    asm volatile(
        "mma.sync.aligned.m16n8k16.row.col.f32.bf16.bf16.f32 "
        "{%0,%1,%2,%3}, {%4,%5,%6,%7}, {%8,%9}, {%0,%1,%2,%3};"
        : "+f"(d[0]), "+f"(d[1]), "+f"(d[2]), "+f"(d[3])
        : "r"(a[0]), "r"(a[1]), "r"(a[2]), "r"(a[3]), "r"(b0), "r"(b1));
}
__device__ __forceinline__ void cp16(uint32_t dst, const void* src) {
    asm volatile("cp.async.cg.shared.global [%0], [%1], 16;" :: "r"(dst), "l"(src));
}
__device__ __forceinline__ void cp_commit() {
    asm volatile("cp.async.commit_group;" ::: "memory");
}
__device__ __forceinline__ void cp_wait1() {
    asm volatile("cp.async.wait_group 1;" ::: "memory");
}

// ---------------------------------------------------------------------------
// Kernel 1: row-normalize + cast to bf16. One block (128 threads) per row.
// ---------------------------------------------------------------------------
__global__ void knorm(const float* __restrict__ x, __nv_bfloat16* __restrict__ xnb) {
    int row = blockIdx.x;
    int t = threadIdx.x;
    float4 v = ((const float4*)(x + (size_t)row * D))[t];
    float s = v.x * v.x + v.y * v.y + v.z * v.z + v.w * v.w;
    #pragma unroll
    for (int o = 16; o; o >>= 1) s += __shfl_xor_sync(0xffffffffu, s, o);
    __shared__ float ws[4];
    if ((t & 31) == 0) ws[t >> 5] = s;
    __syncthreads();
    float inv = rsqrtf(ws[0] + ws[1] + ws[2] + ws[3]);
    __nv_bfloat162 p0 = __floats2bfloat162_rn(v.x * inv, v.y * inv);
    __nv_bfloat162 p1 = __floats2bfloat162_rn(v.z * inv, v.w * inv);
    uint2 o2;
    o2.x = *(uint32_t*)&p0;
    o2.y = *(uint32_t*)&p1;
    ((uint2*)(xnb + (size_t)row * D))[t] = o2;
}

// ---------------------------------------------------------------------------
// Prefetch one K-chunk (chunk index h in [0, NCHUNK)) into B buffer h%3.
// Chunk h covers col tile (h>>3), K window (h&7)*KC. 1024 x 16B, swizzled.
// ---------------------------------------------------------------------------
__device__ __forceinline__ void prefetch_chunk(uint32_t sb, const __nv_bfloat16* xnb,
                                               int colbase, int h, int tid) {
    const uint32_t dstb = sb + SA_BYTES + (uint32_t)(h % 3) * SB_BYTES;
    const int col0 = colbase + (h >> 3) * TNT;
    const int koff = (h & 7) * KC;
    #pragma unroll
    for (int it = 0; it < 4; it++) {
        int idx = tid + it * 256;        // 0..1023 16B chunks
        int n = idx >> 3, c16 = idx & 7;
        uint32_t off = (uint32_t)n * 128 + (uint32_t)c16 * 16;
        uint32_t sw = off ^ ((uint32_t)(n & 7) << 4);
        cp16(dstb + sw, xnb + (size_t)(col0 + n) * D + koff + c16 * 8);
    }
    cp_commit();
}

// ---------------------------------------------------------------------------
// Kernel 2: mma.sync bf16 GEMM (Xn Xn^T) + fused per-row top-5 in registers.
// Grid (64, 2): 64 M-tiles x 2 column halves. 256 threads = 8 warps (4M x 2N).
// Warp tile: 32 rows x 64 cols. 3-stage cp.async pipeline, ONE barrier/chunk.
// ---------------------------------------------------------------------------
__global__ void __launch_bounds__(256, 1)
gemm_topk(const __nv_bfloat16* __restrict__ xnb, float* __restrict__ gtop) {
    extern __shared__ char smem[];
    const uint32_t sb = smem_u32(smem);
    const int tid = threadIdx.x;
    const int wid = tid >> 5, lane = tid & 31;
    const int wm = wid & 3, wn = wid >> 2;
    const int brow = blockIdx.x * TM;
    const int colbase = blockIdx.y * (N / 2);

    const int q = lane >> 3;         // ldmatrix quadrant
    const int lr = lane & 7;         // ldmatrix row-within-quadrant
    const uint32_t swz = (uint32_t)lr << 4;  // 16B-chunk XOR swizzle

    // ---- Load resident A panel: 128 rows x 512 bf16, swizzled ----
    #pragma unroll 8
    for (int it = 0; it < 32; it++) {
        int idx = tid + it * 256;          // 0..8191 16B chunks
        int r = idx >> 6, c16 = idx & 63;
        uint32_t off = (uint32_t)r * 1024 + (uint32_t)c16 * 16;
        uint32_t sw = off ^ ((uint32_t)(r & 7) << 4);
        *(uint4*)(smem + sw) = *(const uint4*)(xnb + (size_t)(brow + r) * D + c16 * 8);
    }

    // ldmatrix base offsets (additive parts; XOR applied at use)
    uint32_t aoff[2], boff[4];
    #pragma unroll
    for (int mt = 0; mt < 2; mt++) {
        int arow = wm * 32 + mt * 16 + (q & 1) * 8 + lr;
        aoff[mt] = (uint32_t)arow * 1024 + (uint32_t)(q >> 1) * 16;
    }
    #pragma unroll
    for (int np = 0; np < 4; np++) {
        int bn = wn * 64 + np * 16 + (q & 1) * 8 + lr;
        boff[np] = (uint32_t)bn * 128 + (uint32_t)(q >> 1) * 16;
    }

    // private top-5 per row-slot (ascending; [0] = smallest kept)
    float tp[4][5];
    #pragma unroll
    for (int s = 0; s < 4; s++)
        #pragma unroll
        for (int i = 0; i < 5; i++) tp[s][i] = -2.f;

    int rowg[4];
    #pragma unroll
    for (int mt = 0; mt < 2; mt++)
        #pragma unroll
        for (int half = 0; half < 2; half++)
            rowg[mt * 2 + half] = brow + wm * 32 + mt * 16 + half * 8 + (lane >> 2);

    // prologue: prefetch chunks 0 and 1 (buffers 0 and 1)
    prefetch_chunk(sb, xnb, colbase, 0, tid);
    prefetch_chunk(sb, xnb, colbase, 1, tid);

    for (int ct = 0; ct < NTILES; ct++) {
        const int col0 = colbase + ct * TNT;

        float acc[2][8][4];
        #pragma unroll
        for (int mt = 0; mt < 2; mt++)
            #pragma unroll
            for (int nt = 0; nt < 8; nt++)
                #pragma unroll
                for (int j = 0; j < 4; j++) acc[mt][nt][j] = 0.f;

        #pragma unroll
        for (int kb = 0; kb < D / KC; kb++) {
            const int g = ct * 8 + kb;

            // chunk-boundary: chunk g arrived (<=1 group pending), all warps
            // done reading buffer (g-1)%3 -> safe to refill it with g+2.
            cp_wait1();
            __syncthreads();
            if (g + 2 < NCHUNK)
                prefetch_chunk(sb, xnb, colbase, g + 2, tid);

            const uint32_t bbase = sb + SA_BYTES + (uint32_t)(g % 3) * SB_BYTES;

            #pragma unroll
            for (int k16 = 0; k16 < 4; k16++) {
                uint32_t a[2][4], b[4][4];
                #pragma unroll
                for (int mt = 0; mt < 2; mt++)
                    ldsm_x4(a[mt], sb + ((aoff[mt] + kb * 128 + k16 * 32) ^ swz));
                #pragma unroll
                for (int np = 0; np < 4; np++)
                    ldsm_x4(b[np], bbase + ((boff[np] + k16 * 32) ^ swz));
                #pragma unroll
                for (int mt = 0; mt < 2; mt++)
                    #pragma unroll
                    for (int nt = 0; nt < 8; nt++) {
                        const int np = nt >> 1, w = nt & 1;
                        mma_bf16(acc[mt][nt], a[mt], b[np][w], b[np][w + 2]);
                    }
            }
        }

        // ---- scan accumulators into private top-5 (register-only) ----
        #pragma unroll
        for (int mt = 0; mt < 2; mt++)
            #pragma unroll
            for (int half = 0; half < 2; half++) {
                const int s = mt * 2 + half;
                const int rg = rowg[s];
                #pragma unroll
                for (int nt = 0; nt < 8; nt++)
                    #pragma unroll
                    for (int j = 0; j < 2; j++) {
                        float v = acc[mt][nt][half * 2 + j];
                        int cg = col0 + wn * 64 + nt * 8 + 2 * (lane & 3) + j;
                        if (cg != rg && v > tp[s][0]) {
                            tp[s][0] = v;
                            #pragma unroll
                            for (int i = 0; i < 4; i++) {
                                if (tp[s][i] > tp[s][i + 1]) {
                                    float tm = tp[s][i];
                                    tp[s][i] = tp[s][i + 1];
                                    tp[s][i + 1] = tm;
                                }
                            }
                        }
                    }
            }
    }

    // ---- merge 8 partial lists per row via SMEM (reuse A area) ----
    __syncthreads();
    float* mrg = (float*)smem;  // [128][40]
    #pragma unroll
    for (int mt = 0; mt < 2; mt++)
        #pragma unroll
        for (int half = 0; half < 2; half++) {
            const int s = mt * 2 + half;
            int rl = wm * 32 + mt * 16 + half * 8 + (lane >> 2);
            int w = wn * 4 + (lane & 3);
            #pragma unroll
            for (int i = 0; i < 5; i++)
                mrg[rl * 40 + w * 5 + i] = tp[s][i];
        }
    __syncthreads();

    if (tid < 128) {
        float t0 = -2.f, t1 = -2.f, t2 = -2.f, t3 = -2.f, t4 = -2.f;
        #pragma unroll 8
        for (int i = 0; i < 40; i++) {
            float v = mrg[tid * 40 + i];
            if (v > t0) {
                t0 = v;
                if (t0 > t1) { float tm = t0; t0 = t1; t1 = tm;
                  if (t1 > t2) { tm = t1; t1 = t2; t2 = tm;
                    if (t2 > t3) { tm = t2; t2 = t3; t3 = tm;
                      if (t3 > t4) { tm = t3; t3 = t4; t4 = tm; } } } }
            }
        }
        float* dst = gtop + (size_t)(brow + tid) * 10 + blockIdx.y * 5;
        dst[0] = t0; dst[1] = t1; dst[2] = t2; dst[3] = t3; dst[4] = t4;
    }
}

// ---------------------------------------------------------------------------
// Kernel 3: merge the two halves' top-5 lists, compute log(mean_rho + eps).
// ---------------------------------------------------------------------------
__global__ void kfinal(const float* __restrict__ gtop, float* __restrict__ lr) {
    int row = blockIdx.x * 256 + threadIdx.x;
    float v[10];
    #pragma unroll
    for (int i = 0; i < 10; i++) v[i] = gtop[(size_t)row * 10 + i];
    float sum = 0.f;
    #pragma unroll
    for (int s = 0; s < KTOP; s++) {
        int bi = 0; float bv = v[0];
        #pragma unroll
        for (int i = 1; i < 10; i++)
            if (v[i] > bv) { bv = v[i]; bi = i; }
        v[bi] = -9.f;
        sum += sqrtf(fmaxf(2.f - 2.f * bv, 0.f));
    }
    lr[row] = logf(sum * (1.f / KTOP) + 1e-8f);
}

// ---------------------------------------------------------------------------
// Kernel 4: out = -mean(logrho)
// ---------------------------------------------------------------------------
__global__ void kred(const float* __restrict__ lr, float* __restrict__ out) {
    int t = threadIdx.x;
    float s = 0.f;
    for (int i = t; i < N; i += 256) s += lr[i];
    #pragma unroll
    for (int o = 16; o; o >>= 1) s += __shfl_xor_sync(0xffffffffu, s, o);
    __shared__ float ws[8];
    if ((t & 31) == 0) ws[t >> 5] = s;
    __syncthreads();
    if (t == 0) {
        float tot = 0.f;
        #pragma unroll
        for (int i = 0; i < 8; i++) tot += ws[i];
        out[0] = -tot / (float)N;
    }
}

// ---------------------------------------------------------------------------
extern "C" void kernel_launch(void* const* d_in, const int* in_sizes, int n_in,
                              void* d_out, int out_size) {
    (void)in_sizes; (void)n_in; (void)out_size;
    const float* x = (const float*)d_in[0];
    float* out = (float*)d_out;

    __nv_bfloat16* xnb; cudaGetSymbolAddress((void**)&xnb, g_xnb);
    float* gtop;        cudaGetSymbolAddress((void**)&gtop, g_top);
    float* lrho;        cudaGetSymbolAddress((void**)&lrho, g_logrho);

    cudaFuncSetAttribute(gemm_topk, cudaFuncAttributeMaxDynamicSharedMemorySize, SMEM_TOTAL);

    knorm<<<N, 128>>>(x, xnb);
    gemm_topk<<<dim3(N / TM, 2), 256, SMEM_TOTAL>>>(xnb, gtop);
    kfinal<<<N / 256, 256>>>(gtop, lrho);
    kred<<<1, 256>>>(lrho, out);
}

// round 12
// speedup vs baseline: 2.4702x; 1.1459x over previous
#include <cuda_runtime.h>
#include <cuda_bf16.h>
#include <math.h>
#include <stdint.h>

#define N 8192
#define D 512
#define TM 128           // M rows per CTA
#define TNT 256          // cols per column tile
#define KC 64            // K chunk per B SMEM tile
#define KTOP 5
#define NTILES ((N / 2) / TNT)   // 16 column tiles per CTA (half the matrix)
#define NTHREADS 512

// Scratch (no cudaMalloc allowed)
static __device__ __nv_bfloat16 g_xnb[(size_t)N * D];   // 8 MB normalized rows, bf16
static __device__ float g_top[(size_t)N * 10];          // per-row top5 from each half
static __device__ float g_logrho[N];

// SMEM: A panel 128 KB resident + 2x 32 KB B buffers (merge area reuses A)
#define SA_BYTES (128 * 1024)
#define SB_BYTES (32 * 1024)
#define SMEM_TOTAL (SA_BYTES + 2 * SB_BYTES)   // 192 KB

// ---- PTX helpers ------------------------------------------------------------
__device__ __forceinline__ uint32_t smem_u32(const void* p) {
    uint32_t a;
    asm("{ .reg .u64 t; cvta.to.shared.u64 t, %1; cvt.u32.u64 %0, t; }" : "=r"(a) : "l"(p));
    return a;
}
__device__ __forceinline__ void ldsm_x4(uint32_t* r, uint32_t addr) {
    asm volatile("ldmatrix.sync.aligned.m8n8.x4.shared.b16 {%0,%1,%2,%3}, [%4];"
                 : "=r"(r[0]), "=r"(r[1]), "=r"(r[2]), "=r"(r[3]) : "r"(addr));
}
__device__ __forceinline__ void mma_bf16(float* d, const uint32_t* a,
                                         uint32_t b0, uint32_t b1) {
    asm volatile(
        "mma.sync.aligned.m16n8k16.row.col.f32.bf16.bf16.f32 "
        "{%0,%1,%2,%3}, {%4,%5,%6,%7}, {%8,%9}, {%0,%1,%2,%3};"
        : "+f"(d[0]), "+f"(d[1]), "+f"(d[2]), "+f"(d[3])
        : "r"(a[0]), "r"(a[1]), "r"(a[2]), "r"(a[3]), "r"(b0), "r"(b1));
}
__device__ __forceinline__ void cp16(uint32_t dst, const void* src) {
    asm volatile("cp.async.cg.shared.global [%0], [%1], 16;" :: "r"(dst), "l"(src));
}
__device__ __forceinline__ void cp_commit() {
    asm volatile("cp.async.commit_group;" ::: "memory");
}
__device__ __forceinline__ void cp_wait1() {
    asm volatile("cp.async.wait_group 1;" ::: "memory");
}
__device__ __forceinline__ void cp_wait0() {
    asm volatile("cp.async.wait_group 0;" ::: "memory");
}

// ---------------------------------------------------------------------------
// Kernel 1: row-normalize + cast to bf16. One block (128 threads) per row.
// ---------------------------------------------------------------------------
__global__ void knorm(const float* __restrict__ x, __nv_bfloat16* __restrict__ xnb) {
    int row = blockIdx.x;
    int t = threadIdx.x;
    float4 v = ((const float4*)(x + (size_t)row * D))[t];
    float s = v.x * v.x + v.y * v.y + v.z * v.z + v.w * v.w;
    #pragma unroll
    for (int o = 16; o; o >>= 1) s += __shfl_xor_sync(0xffffffffu, s, o);
    __shared__ float ws[4];
    if ((t & 31) == 0) ws[t >> 5] = s;
    __syncthreads();
    float inv = rsqrtf(ws[0] + ws[1] + ws[2] + ws[3]);
    __nv_bfloat162 p0 = __floats2bfloat162_rn(v.x * inv, v.y * inv);
    __nv_bfloat162 p1 = __floats2bfloat162_rn(v.z * inv, v.w * inv);
    uint2 o2;
    o2.x = *(uint32_t*)&p0;
    o2.y = *(uint32_t*)&p1;
    ((uint2*)(xnb + (size_t)row * D))[t] = o2;
}

// ---------------------------------------------------------------------------
// Kernel 2: mma.sync bf16 GEMM (Xn Xn^T) + fused per-row top-5 in registers.
// Grid (64, 2): 64 M-tiles x 2 column halves. 512 threads = 16 warps (4M x 4N).
// Warp tile: 32 rows x 64 cols (same per-thread shape as the 275us kernel);
// 4 warps/SMSP for latency hiding. B tile 256 cols, double-buffered.
// ---------------------------------------------------------------------------
__global__ void __launch_bounds__(NTHREADS, 1)
gemm_topk(const __nv_bfloat16* __restrict__ xnb, float* __restrict__ gtop) {
    extern __shared__ char smem[];
    const uint32_t sb = smem_u32(smem);
    const int tid = threadIdx.x;
    const int wid = tid >> 5, lane = tid & 31;
    const int wm = wid & 3;          // 4 M-groups of 32 rows
    const int wn = wid >> 2;         // 4 N-groups of 64 cols
    const int brow = blockIdx.x * TM;
    const int colbase = blockIdx.y * (N / 2);

    const int q = lane >> 3;         // ldmatrix quadrant
    const int lr = lane & 7;         // ldmatrix row-within-quadrant
    const uint32_t swz = (uint32_t)lr << 4;  // 16B-chunk XOR swizzle

    // ---- Load resident A panel: 128 rows x 512 bf16, swizzled ----
    #pragma unroll 8
    for (int it = 0; it < 16; it++) {
        int idx = tid + it * NTHREADS;     // 0..8191 16B chunks
        int r = idx >> 6, c16 = idx & 63;
        uint32_t off = (uint32_t)r * 1024 + (uint32_t)c16 * 16;
        uint32_t sw = off ^ ((uint32_t)(r & 7) << 4);
        *(uint4*)(smem + sw) = *(const uint4*)(xnb + (size_t)(brow + r) * D + c16 * 8);
    }

    // ldmatrix base offsets (additive parts; XOR applied at use)
    uint32_t aoff[2], boff[4];
    #pragma unroll
    for (int mt = 0; mt < 2; mt++) {
        int arow = wm * 32 + mt * 16 + (q & 1) * 8 + lr;
        aoff[mt] = (uint32_t)arow * 1024 + (uint32_t)(q >> 1) * 16;
    }
    #pragma unroll
    for (int np = 0; np < 4; np++) {
        int bn = wn * 64 + np * 16 + (q & 1) * 8 + lr;
        boff[np] = (uint32_t)bn * 128 + (uint32_t)(q >> 1) * 16;
    }

    // private top-5 per row-slot (ascending; [0] = smallest kept)
    float tp[4][5];
    #pragma unroll
    for (int s = 0; s < 4; s++)
        #pragma unroll
        for (int i = 0; i < 5; i++) tp[s][i] = -2.f;

    int rowg[4];
    #pragma unroll
    for (int mt = 0; mt < 2; mt++)
        #pragma unroll
        for (int half = 0; half < 2; half++)
            rowg[mt * 2 + half] = brow + wm * 32 + mt * 16 + half * 8 + (lane >> 2);

    // preload tile0 chunk0 into buf0 (32 KB = 2048 16B chunks, 4 per thread)
    {
        #pragma unroll
        for (int it = 0; it < 4; it++) {
            int idx = tid + it * NTHREADS;
            int n = idx >> 3, c16 = idx & 7;
            uint32_t off = (uint32_t)n * 128 + (uint32_t)c16 * 16;
            uint32_t sw = off ^ ((uint32_t)(n & 7) << 4);
            cp16(sb + SA_BYTES + sw, xnb + (size_t)(colbase + n) * D + c16 * 8);
        }
        cp_commit();
    }

    for (int ct = 0; ct < NTILES; ct++) {
        const int col0 = colbase + ct * TNT;

        float acc[2][8][4];
        #pragma unroll
        for (int mt = 0; mt < 2; mt++)
            #pragma unroll
            for (int nt = 0; nt < 8; nt++)
                #pragma unroll
                for (int j = 0; j < 4; j++) acc[mt][nt][j] = 0.f;

        #pragma unroll
        for (int kb = 0; kb < D / KC; kb++) {
            // prefetch next chunk (or next tile's chunk0) into the other buffer
            if (kb < 7) {
                uint32_t dstb = sb + SA_BYTES + ((kb + 1) & 1) * SB_BYTES;
                #pragma unroll
                for (int it = 0; it < 4; it++) {
                    int idx = tid + it * NTHREADS;
                    int n = idx >> 3, c16 = idx & 7;
                    uint32_t off = (uint32_t)n * 128 + (uint32_t)c16 * 16;
                    uint32_t sw = off ^ ((uint32_t)(n & 7) << 4);
                    cp16(dstb + sw, xnb + (size_t)(col0 + n) * D + (kb + 1) * KC + c16 * 8);
                }
                cp_commit();
                cp_wait1();
            } else if (ct + 1 < NTILES) {
                uint32_t dstb = sb + SA_BYTES;  // buf0
                int ncol0 = colbase + (ct + 1) * TNT;
                #pragma unroll
                for (int it = 0; it < 4; it++) {
                    int idx = tid + it * NTHREADS;
                    int n = idx >> 3, c16 = idx & 7;
                    uint32_t off = (uint32_t)n * 128 + (uint32_t)c16 * 16;
                    uint32_t sw = off ^ ((uint32_t)(n & 7) << 4);
                    cp16(dstb + sw, xnb + (size_t)(ncol0 + n) * D + c16 * 8);
                }
                cp_commit();
                cp_wait1();
            } else {
                cp_wait0();
            }
            __syncthreads();

            const uint32_t bbase = sb + SA_BYTES + (kb & 1) * SB_BYTES;

            #pragma unroll
            for (int k16 = 0; k16 < 4; k16++) {
                uint32_t a[2][4], b[4][4];
                #pragma unroll
                for (int mt = 0; mt < 2; mt++)
                    ldsm_x4(a[mt], sb + ((aoff[mt] + kb * 128 + k16 * 32) ^ swz));
                #pragma unroll
                for (int np = 0; np < 4; np++)
                    ldsm_x4(b[np], bbase + ((boff[np] + k16 * 32) ^ swz));
                #pragma unroll
                for (int mt = 0; mt < 2; mt++)
                    #pragma unroll
                    for (int nt = 0; nt < 8; nt++) {
                        const int np = nt >> 1, w = nt & 1;
                        mma_bf16(acc[mt][nt], a[mt], b[np][w], b[np][w + 2]);
                    }
            }
            __syncthreads();  // all reads of this buffer done before it is refilled
        }

        // ---- scan accumulators into private top-5 (register-only) ----
        #pragma unroll
        for (int mt = 0; mt < 2; mt++)
            #pragma unroll
            for (int half = 0; half < 2; half++) {
                const int s = mt * 2 + half;
                const int rg = rowg[s];
                #pragma unroll
                for (int nt = 0; nt < 8; nt++)
                    #pragma unroll
                    for (int j = 0; j < 2; j++) {
                        float v = acc[mt][nt][half * 2 + j];
                        int cg = col0 + wn * 64 + nt * 8 + 2 * (lane & 3) + j;
                        if (cg != rg && v > tp[s][0]) {
                            tp[s][0] = v;
                            #pragma unroll
                            for (int i = 0; i < 4; i++) {
                                if (tp[s][i] > tp[s][i + 1]) {
                                    float tm = tp[s][i];
                                    tp[s][i] = tp[s][i + 1];
                                    tp[s][i + 1] = tm;
                                }
                            }
                        }
                    }
            }
    }

    // ---- merge 16 partial lists per row via SMEM (reuse A area) ----
    __syncthreads();
    float* mrg = (float*)smem;  // [128][80]
    #pragma unroll
    for (int mt = 0; mt < 2; mt++)
        #pragma unroll
        for (int half = 0; half < 2; half++) {
            const int s = mt * 2 + half;
            int rl = wm * 32 + mt * 16 + half * 8 + (lane >> 2);
            int w = wn * 4 + (lane & 3);     // 16 lists per row
            #pragma unroll
            for (int i = 0; i < 5; i++)
                mrg[rl * 80 + w * 5 + i] = tp[s][i];
        }
    __syncthreads();

    if (tid < 128) {
        float t0 = -2.f, t1 = -2.f, t2 = -2.f, t3 = -2.f, t4 = -2.f;
        #pragma unroll 8
        for (int i = 0; i < 80; i++) {
            float v = mrg[tid * 80 + i];
            if (v > t0) {
                t0 = v;
                if (t0 > t1) { float tm = t0; t0 = t1; t1 = tm;
                  if (t1 > t2) { tm = t1; t1 = t2; t2 = tm;
                    if (t2 > t3) { tm = t2; t2 = t3; t3 = tm;
                      if (t3 > t4) { tm = t3; t3 = t4; t4 = tm; } } } }
            }
        }
        float* dst = gtop + (size_t)(brow + tid) * 10 + blockIdx.y * 5;
        dst[0] = t0; dst[1] = t1; dst[2] = t2; dst[3] = t3; dst[4] = t4;
    }
}

// ---------------------------------------------------------------------------
// Kernel 3: merge the two halves' top-5 lists, compute log(mean_rho + eps).
// ---------------------------------------------------------------------------
__global__ void kfinal(const float* __restrict__ gtop, float* __restrict__ lr) {
    int row = blockIdx.x * 256 + threadIdx.x;
    float v[10];
    #pragma unroll
    for (int i = 0; i < 10; i++) v[i] = gtop[(size_t)row * 10 + i];
    float sum = 0.f;
    #pragma unroll
    for (int s = 0; s < KTOP; s++) {
        int bi = 0; float bv = v[0];
        #pragma unroll
        for (int i = 1; i < 10; i++)
            if (v[i] > bv) { bv = v[i]; bi = i; }
        v[bi] = -9.f;
        sum += sqrtf(fmaxf(2.f - 2.f * bv, 0.f));
    }
    lr[row] = logf(sum * (1.f / KTOP) + 1e-8f);
}

// ---------------------------------------------------------------------------
// Kernel 4: out = -mean(logrho)
// ---------------------------------------------------------------------------
__global__ void kred(const float* __restrict__ lr, float* __restrict__ out) {
    int t = threadIdx.x;
    float s = 0.f;
    for (int i = t; i < N; i += 256) s += lr[i];
    #pragma unroll
    for (int o = 16; o; o >>= 1) s += __shfl_xor_sync(0xffffffffu, s, o);
    __shared__ float ws[8];
    if ((t & 31) == 0) ws[t >> 5] = s;
    __syncthreads();
    if (t == 0) {
        float tot = 0.f;
        #pragma unroll
        for (int i = 0; i < 8; i++) tot += ws[i];
        out[0] = -tot / (float)N;
    }
}

// ---------------------------------------------------------------------------
extern "C" void kernel_launch(void* const* d_in, const int* in_sizes, int n_in,
                              void* d_out, int out_size) {
    (void)in_sizes; (void)n_in; (void)out_size;
    const float* x = (const float*)d_in[0];
    float* out = (float*)d_out;

    __nv_bfloat16* xnb; cudaGetSymbolAddress((void**)&xnb, g_xnb);
    float* gtop;        cudaGetSymbolAddress((void**)&gtop, g_top);
    float* lrho;        cudaGetSymbolAddress((void**)&lrho, g_logrho);

    cudaFuncSetAttribute(gemm_topk, cudaFuncAttributeMaxDynamicSharedMemorySize, SMEM_TOTAL);

    knorm<<<N, 128>>>(x, xnb);
    gemm_topk<<<dim3(N / TM, 2), NTHREADS, SMEM_TOTAL>>>(xnb, gtop);
    kfinal<<<N / 256, 256>>>(gtop, lrho);
    kred<<<1, 256>>>(lrho, out);
}